// round 12
// baseline (speedup 1.0000x reference)
#include <cuda_runtime.h>
#include <cuda_fp16.h>
#include <math.h>

#define CG 128
#define CN 64
#define CS 64
#define KK 27
#define EPS 1e-5f

#define MAX_NG 60000
#define MAX_NX 200000

// -------- scratch (device globals, zero-initialized at module load) --------
// Invariant: every kernel_launch invocation leaves d_S, d_colstats, d_zstats
// zeroed for the next invocation (output_kernel resets during S read).
__device__ __half d_fg[MAX_NG * CN];
__device__ __half d_fs[MAX_NG * CN];
__device__ float d_z[MAX_NG];
__device__ __half d_att_h[MAX_NG];     // fp16 att: 120KB, fits in L1
__device__ float d_S[MAX_NX * KK];
__device__ float d_colstats[4 * CN];
__device__ float d_zstats[2];

// ---- packed f32x2 helpers (sm_103a FFMA2 via PTX) ----
__device__ __forceinline__ unsigned long long fma2(
    unsigned long long a, unsigned long long b, unsigned long long c) {
    unsigned long long d;
    asm("fma.rn.f32x2 %0, %1, %2, %3;" : "=l"(d) : "l"(a), "l"(b), "l"(c));
    return d;
}
__device__ __forceinline__ unsigned long long dup2(float v) {
    unsigned long long d;
    asm("mov.b64 %0, {%1, %1};" : "=l"(d) : "r"(__float_as_uint(v)));
    return d;
}
union P2 { unsigned long long u; float2 f; };
union W4 { float4 f4; unsigned long long u[2]; };
union H4 { uint4 u; __half2 h[4]; };

// ============ fg = g @ Wg (Ng x 128 @ 128 x 64), FFMA2, fused stats ============
__global__ __launch_bounds__(256) void gemm_g_kernel(
    const float* __restrict__ g, const float* __restrict__ Wg, int Ng) {
    __shared__ float Wsm[CG * CN];
    int t = threadIdx.x;
    for (int i = t; i < CG * CN; i += 256) Wsm[i] = Wg[i];
    __syncthreads();

    const int tr = t >> 3;
    const int c0 = (t & 7) * 8;
    const int r0 = blockIdx.x * 128 + tr * 4;

    unsigned long long acc[4][4];
#pragma unroll
    for (int j = 0; j < 4; j++)
#pragma unroll
        for (int i = 0; i < 4; i++) acc[j][i] = 0ull;

    bool v[4];
    const float4* gp[4];
#pragma unroll
    for (int j = 0; j < 4; j++) {
        v[j] = (r0 + j) < Ng;
        gp[j] = (const float4*)(g + (size_t)(r0 + j) * CG);
    }
    const float4 zero4 = make_float4(0.f, 0.f, 0.f, 0.f);

#pragma unroll 2
    for (int k4 = 0; k4 < CG / 4; k4++) {
        float4 a[4];
#pragma unroll
        for (int j = 0; j < 4; j++) a[j] = v[j] ? __ldcs(&gp[j][k4]) : zero4;
#pragma unroll
        for (int kk = 0; kk < 4; kk++) {
            int k = k4 * 4 + kk;
            W4 w0, w1;
            w0.f4 = *(const float4*)&Wsm[k * CN + c0];
            w1.f4 = *(const float4*)&Wsm[k * CN + c0 + 4];
#pragma unroll
            for (int j = 0; j < 4; j++) {
                unsigned long long av = dup2((&a[j].x)[kk]);
                acc[j][0] = fma2(av, w0.u[0], acc[j][0]);
                acc[j][1] = fma2(av, w0.u[1], acc[j][1]);
                acc[j][2] = fma2(av, w1.u[0], acc[j][2]);
                acc[j][3] = fma2(av, w1.u[1], acc[j][3]);
            }
        }
    }

    float csum[8], csq[8];
#pragma unroll
    for (int i = 0; i < 8; i++) { csum[i] = 0.f; csq[i] = 0.f; }
#pragma unroll
    for (int j = 0; j < 4; j++) {
        float av[8];
#pragma unroll
        for (int i = 0; i < 4; i++) {
            P2 p; p.u = acc[j][i];
            av[2 * i] = p.f.x; av[2 * i + 1] = p.f.y;
        }
        if (r0 + j < Ng) {
            H4 st;
#pragma unroll
            for (int i = 0; i < 4; i++)
                st.h[i] = __floats2half2_rn(av[2 * i], av[2 * i + 1]);
            *(uint4*)&d_fg[(size_t)(r0 + j) * CN + c0] = st.u;
        }
#pragma unroll
        for (int i = 0; i < 8; i++) { csum[i] += av[i]; csq[i] += av[i] * av[i]; }
    }

    __syncthreads();
    float* s_sum = Wsm;
    float* s_sq  = Wsm + 2048;
#pragma unroll
    for (int i = 0; i < 8; i++) {
        s_sum[tr * 64 + c0 + i] = csum[i];
        s_sq[tr * 64 + c0 + i]  = csq[i];
    }
    __syncthreads();
    int col = t & 63, seg = t >> 6;
    float v1 = 0.f, v2 = 0.f;
#pragma unroll
    for (int r = 0; r < 8; r++) {
        v1 += s_sum[(seg * 8 + r) * 64 + col];
        v2 += s_sq[(seg * 8 + r) * 64 + col];
    }
    __syncthreads();
    s_sum[seg * 64 + col] = v1;
    s_sq[seg * 64 + col]  = v2;
    __syncthreads();
    if (t < 64) {
        float a = s_sum[t] + s_sum[64 + t] + s_sum[128 + t] + s_sum[192 + t];
        float b = s_sq[t]  + s_sq[64 + t]  + s_sq[128 + t]  + s_sq[192 + t];
        atomicAdd(&d_colstats[t], a);
        atomicAdd(&d_colstats[64 + t], b);
    }
}

// ============ fs = x[down_idx] @ Ws (Ng x 64 @ 64 x 64), FFMA2, fused stats ============
__global__ __launch_bounds__(256) void gemm_s_kernel(
    const float* __restrict__ x, const int* __restrict__ down_idx,
    const float* __restrict__ Ws, int Ng) {
    __shared__ float Wsm[CS * CN];
    __shared__ float s_red[4096];
    __shared__ int ds[128];
    int t = threadIdx.x;
    for (int i = t; i < CS * CN; i += 256) Wsm[i] = Ws[i];
    int rbase = blockIdx.x * 128;
    if (t < 128) ds[t] = (rbase + t < Ng) ? down_idx[rbase + t] : 0;
    __syncthreads();

    const int tr = t >> 3;
    const int c0 = (t & 7) * 8;
    const int r0 = rbase + tr * 4;

    unsigned long long acc[4][4];
#pragma unroll
    for (int j = 0; j < 4; j++)
#pragma unroll
        for (int i = 0; i < 4; i++) acc[j][i] = 0ull;

    bool v[4];
    const float4* xp[4];
#pragma unroll
    for (int j = 0; j < 4; j++) {
        v[j] = (r0 + j) < Ng;
        xp[j] = (const float4*)(x + (size_t)ds[tr * 4 + j] * CS);
    }
    const float4 zero4 = make_float4(0.f, 0.f, 0.f, 0.f);

#pragma unroll 2
    for (int k4 = 0; k4 < CS / 4; k4++) {
        float4 a[4];
#pragma unroll
        for (int j = 0; j < 4; j++) a[j] = v[j] ? __ldg(&xp[j][k4]) : zero4;
#pragma unroll
        for (int kk = 0; kk < 4; kk++) {
            int k = k4 * 4 + kk;
            W4 w0, w1;
            w0.f4 = *(const float4*)&Wsm[k * CN + c0];
            w1.f4 = *(const float4*)&Wsm[k * CN + c0 + 4];
#pragma unroll
            for (int j = 0; j < 4; j++) {
                unsigned long long av = dup2((&a[j].x)[kk]);
                acc[j][0] = fma2(av, w0.u[0], acc[j][0]);
                acc[j][1] = fma2(av, w0.u[1], acc[j][1]);
                acc[j][2] = fma2(av, w1.u[0], acc[j][2]);
                acc[j][3] = fma2(av, w1.u[1], acc[j][3]);
            }
        }
    }

    float csum[8], csq[8];
#pragma unroll
    for (int i = 0; i < 8; i++) { csum[i] = 0.f; csq[i] = 0.f; }
#pragma unroll
    for (int j = 0; j < 4; j++) {
        float av[8];
#pragma unroll
        for (int i = 0; i < 4; i++) {
            P2 p; p.u = acc[j][i];
            av[2 * i] = p.f.x; av[2 * i + 1] = p.f.y;
        }
        if (r0 + j < Ng) {
            H4 st;
#pragma unroll
            for (int i = 0; i < 4; i++)
                st.h[i] = __floats2half2_rn(av[2 * i], av[2 * i + 1]);
            *(uint4*)&d_fs[(size_t)(r0 + j) * CN + c0] = st.u;
        }
#pragma unroll
        for (int i = 0; i < 8; i++) { csum[i] += av[i]; csq[i] += av[i] * av[i]; }
    }

    float* s_sum = s_red;
    float* s_sq  = s_red + 2048;
#pragma unroll
    for (int i = 0; i < 8; i++) {
        s_sum[tr * 64 + c0 + i] = csum[i];
        s_sq[tr * 64 + c0 + i]  = csq[i];
    }
    __syncthreads();
    int col = t & 63, seg = t >> 6;
    float v1 = 0.f, v2 = 0.f;
#pragma unroll
    for (int r = 0; r < 8; r++) {
        v1 += s_sum[(seg * 8 + r) * 64 + col];
        v2 += s_sq[(seg * 8 + r) * 64 + col];
    }
    __syncthreads();
    s_sum[seg * 64 + col] = v1;
    s_sq[seg * 64 + col]  = v2;
    __syncthreads();
    if (t < 64) {
        float a = s_sum[t] + s_sum[64 + t] + s_sum[128 + t] + s_sum[192 + t];
        float b = s_sq[t]  + s_sq[64 + t]  + s_sq[128 + t]  + s_sq[192 + t];
        atomicAdd(&d_colstats[128 + t], a);
        atomicAdd(&d_colstats[192 + t], b);
    }
}

// -------- fuse: z = (relu(bn_g(fg)) + relu(bn_s(fs))) . Wc; z-stats --------
__global__ __launch_bounds__(256) void fuse_kernel(
    const float* __restrict__ Wc,
    const float* __restrict__ gg, const float* __restrict__ bg,
    const float* __restrict__ gs, const float* __restrict__ bs, int Ng) {
    __shared__ float wc[CN], sgn[CN], bgn[CN], ssn[CN], bsn[CN];
    __shared__ float zs[8][2];
    int t = threadIdx.x;
    if (t < 128) {
        const int c = t & 63;
        const int br = t >> 6;
        float sum = d_colstats[br * 128 + c];
        float sq  = d_colstats[br * 128 + 64 + c];
        const float inv = 1.f / (float)Ng;
        float mu = sum * inv;
        float var = sq * inv - mu * mu;
        float gam = br ? __ldg(&gs[c]) : __ldg(&gg[c]);
        float bet = br ? __ldg(&bs[c]) : __ldg(&bg[c]);
        float sc = gam * rsqrtf(var + EPS);
        if (br == 0) { sgn[c] = sc; bgn[c] = bet - mu * sc; wc[c] = __ldg(&Wc[c]); }
        else         { ssn[c] = sc; bsn[c] = bet - mu * sc; }
    }
    __syncthreads();

    const int wid = t >> 5, lane = t & 31;
    const int rgrp = lane >> 3;
    const int cg = (lane & 7) * 8;
    float bsum = 0.f, bsq = 0.f;

    for (int rowb = (blockIdx.x * 8 + wid) * 8; rowb < Ng; rowb += gridDim.x * 64) {
        int row[2] = { rowb + rgrp, rowb + 4 + rgrp };
        H4 fgv[2], fsv[2];
#pragma unroll
        for (int q = 0; q < 2; q++) {
            if (row[q] < Ng) {
                fgv[q].u = __ldcs((const uint4*)&d_fg[(size_t)row[q] * CN + cg]);
                fsv[q].u = __ldcs((const uint4*)&d_fs[(size_t)row[q] * CN + cg]);
            }
        }
#pragma unroll
        for (int q = 0; q < 2; q++) {
            float part = 0.f;
            if (row[q] < Ng) {
#pragma unroll
                for (int i = 0; i < 4; i++) {
                    float2 f2 = __half22float2(fgv[q].h[i]);
                    float2 s2 = __half22float2(fsv[q].h[i]);
                    int c = cg + 2 * i;
                    float h0 = fmaxf(f2.x * sgn[c] + bgn[c], 0.f) + fmaxf(s2.x * ssn[c] + bsn[c], 0.f);
                    float h1 = fmaxf(f2.y * sgn[c + 1] + bgn[c + 1], 0.f) + fmaxf(s2.y * ssn[c + 1] + bsn[c + 1], 0.f);
                    part += h0 * wc[c] + h1 * wc[c + 1];
                }
            }
#pragma unroll
            for (int o = 4; o > 0; o >>= 1) part += __shfl_xor_sync(0xffffffffu, part, o);
            if ((lane & 7) == 0 && row[q] < Ng) {
                d_z[row[q]] = part;
                bsum += part;
                bsq += part * part;
            }
        }
    }
    bsum += __shfl_down_sync(0xffffffffu, bsum, 16);
    bsum += __shfl_down_sync(0xffffffffu, bsum, 8);
    bsq  += __shfl_down_sync(0xffffffffu, bsq, 16);
    bsq  += __shfl_down_sync(0xffffffffu, bsq, 8);
    if (lane == 0) { zs[wid][0] = bsum; zs[wid][1] = bsq; }
    __syncthreads();
    if (t == 0) {
        float a = 0.f, q = 0.f;
#pragma unroll
        for (int w = 0; w < 8; w++) { a += zs[w][0]; q += zs[w][1]; }
        atomicAdd(&d_zstats[0], a);
        atomicAdd(&d_zstats[1], q);
    }
}

// -------- att = sigmoid(bn(z)) -> fp16 (120KB: L1-resident in scatter) --------
__global__ void att_kernel(const float* __restrict__ gamma_c,
                           const float* __restrict__ beta_c, int Ng, float invNg) {
    float mu = d_zstats[0] * invNg;
    float var = d_zstats[1] * invNg - mu * mu;
    float rs = rsqrtf(var + EPS) * __ldg(&gamma_c[0]);
    float bc = __ldg(&beta_c[0]) - mu * rs;
    int i2 = (blockIdx.x * blockDim.x + threadIdx.x) * 2;
    if (i2 + 1 < Ng) {
        float2 z2 = *(const float2*)&d_z[i2];
        float a0 = 1.f / (1.f + __expf(-(z2.x * rs + bc)));
        float a1 = 1.f / (1.f + __expf(-(z2.y * rs + bc)));
        *(__half2*)&d_att_h[i2] = __floats2half2_rn(a0, a1);
    } else if (i2 < Ng) {
        float a0 = 1.f / (1.f + __expf(-(d_z[i2] * rs + bc)));
        d_att_h[i2] = __float2half_rn(a0);
    }
}

// -------- scatter: gather fp16 att (L1-resident), scatter into S --------
__global__ void scatter_kernel(const int* __restrict__ pin,
                               const int* __restrict__ pout, int P) {
    int i4 = (blockIdx.x * blockDim.x + threadIdx.x) * 4;
    int k = blockIdx.y;
    if (i4 + 3 < P) {
        uint4 pi = *(const uint4*)&pin[(size_t)k * P + i4];
        uint4 po = *(const uint4*)&pout[(size_t)k * P + i4];
        float a0 = __half2float(d_att_h[pi.x]);
        float a1 = __half2float(d_att_h[pi.y]);
        float a2 = __half2float(d_att_h[pi.z]);
        float a3 = __half2float(d_att_h[pi.w]);
        atomicAdd(&d_S[(size_t)po.x * KK + k], a0);
        atomicAdd(&d_S[(size_t)po.y * KK + k], a1);
        atomicAdd(&d_S[(size_t)po.z * KK + k], a2);
        atomicAdd(&d_S[(size_t)po.w * KK + k], a3);
    } else {
        for (int i = i4; i < P; i++) {
            float a = __half2float(d_att_h[__ldg(&pin[(size_t)k * P + i])]);
            atomicAdd(&d_S[(size_t)__ldg(&pout[(size_t)k * P + i]) * KK + k], a);
        }
    }
}

// -------- out = x * (S @ W_inv + b_inv); warp = 4 rows/pass (lower regs, higher occ) --------
__global__ __launch_bounds__(256) void output_kernel(
    const float* __restrict__ x, const float* __restrict__ Winv,
    const float* __restrict__ binv, float* __restrict__ out, int Nx) {
    __shared__ float w[KK * CN];
    __shared__ float bb[CN];
    int t = threadIdx.x;
    for (int i = t; i < KK * CN; i += 256) w[i] = Winv[i];
    if (t < CN) bb[t] = binv[t];
    if (blockIdx.x == 0) {
        d_colstats[t] = 0.f;
        if (t < 2) d_zstats[t] = 0.f;
    }
    __syncthreads();
    const int wid = t >> 5, lane = t & 31;
    const int c = 2 * lane;
    const int r0 = (blockIdx.x * 8 + wid) * 4;
    if (r0 >= Nx) return;

    float sv[4];
    float2 xv[4];
#pragma unroll
    for (int j = 0; j < 4; j++)
        sv[j] = (lane < KK && r0 + j < Nx) ? __ldcs(&d_S[(size_t)(r0 + j) * KK + lane]) : 0.f;
#pragma unroll
    for (int j = 0; j < 4; j++)
        xv[j] = (r0 + j < Nx) ? __ldcs((const float2*)&x[(size_t)(r0 + j) * CS + c])
                              : make_float2(0.f, 0.f);
    // reset S for next invocation (read-before-write in program order)
#pragma unroll
    for (int j = 0; j < 4; j++)
        if (lane < KK && r0 + j < Nx) d_S[(size_t)(r0 + j) * KK + lane] = 0.f;

    float2 acc[4];
    const float b0 = bb[c], b1 = bb[c + 1];
#pragma unroll
    for (int j = 0; j < 4; j++) { acc[j].x = b0; acc[j].y = b1; }

#pragma unroll
    for (int k = 0; k < KK; k++) {
        float2 wk = *(const float2*)&w[k * CN + c];
#pragma unroll
        for (int j = 0; j < 4; j++) {
            float sk = __shfl_sync(0xffffffffu, sv[j], k);
            acc[j].x = fmaf(sk, wk.x, acc[j].x);
            acc[j].y = fmaf(sk, wk.y, acc[j].y);
        }
    }
#pragma unroll
    for (int j = 0; j < 4; j++) {
        if (r0 + j < Nx) {
            float2 o;
            o.x = xv[j].x * acc[j].x;
            o.y = xv[j].y * acc[j].y;
            __stcs((float2*)&out[(size_t)(r0 + j) * CS + c], o);
        }
    }
}

extern "C" void kernel_launch(void* const* d_in, const int* in_sizes, int n_in,
                              void* d_out, int out_size) {
    const float* g        = (const float*)d_in[0];
    const float* x        = (const float*)d_in[1];
    const int*   down_idx = (const int*)d_in[2];
    const int*   pairs_in = (const int*)d_in[3];
    const int*   pairs_out= (const int*)d_in[4];
    const float* Wg       = (const float*)d_in[5];
    const float* Ws       = (const float*)d_in[6];
    const float* Wc       = (const float*)d_in[7];
    const float* W_inv    = (const float*)d_in[8];
    const float* b_inv    = (const float*)d_in[9];
    const float* gamma_g  = (const float*)d_in[10];
    const float* beta_g   = (const float*)d_in[11];
    const float* gamma_s  = (const float*)d_in[12];
    const float* beta_s   = (const float*)d_in[13];
    const float* gamma_c  = (const float*)d_in[14];
    const float* beta_c   = (const float*)d_in[15];

    int Ng = in_sizes[0] / CG;
    int Nx = in_sizes[1] / CS;
    int KP = in_sizes[3];
    int P  = KP / KK;

    gemm_g_kernel<<<(Ng + 127) / 128, 256>>>(g, Wg, Ng);
    gemm_s_kernel<<<(Ng + 127) / 128, 256>>>(x, down_idx, Ws, Ng);
    fuse_kernel<<<(Ng + 63) / 64, 256>>>(Wc, gamma_g, beta_g, gamma_s, beta_s, Ng);
    att_kernel<<<((Ng + 1) / 2 + 255) / 256, 256>>>(gamma_c, beta_c, Ng, 1.f / (float)Ng);
    dim3 sgrid(((P + 3) / 4 + 255) / 256, KK);
    scatter_kernel<<<sgrid, 256>>>(pairs_in, pairs_out, P);
    output_kernel<<<(Nx + 31) / 32, 256>>>(x, W_inv, b_inv, (float*)d_out, Nx);
}

// round 13
// speedup vs baseline: 1.1596x; 1.1596x over previous
#include <cuda_runtime.h>
#include <cuda_fp16.h>
#include <math.h>

#define CG 128
#define CN 64
#define CS 64
#define KK 27
#define EPS 1e-5f

#define MAX_NG 60000
#define MAX_NX 200000

// -------- scratch (device globals, zero-initialized at module load) --------
// Invariant: every kernel_launch invocation leaves d_S, d_colstats, d_zstats
// zeroed for the next invocation (output_kernel resets during S read).
__device__ __half d_fg[MAX_NG * CN];
__device__ __half d_fs[MAX_NG * CN];
__device__ float d_z[MAX_NG];
__device__ float d_S[MAX_NX * KK];
__device__ float d_colstats[4 * CN];
__device__ float d_zstats[2];

// ---- packed f32x2 helpers (sm_103a FFMA2 via PTX) ----
__device__ __forceinline__ unsigned long long fma2(
    unsigned long long a, unsigned long long b, unsigned long long c) {
    unsigned long long d;
    asm("fma.rn.f32x2 %0, %1, %2, %3;" : "=l"(d) : "l"(a), "l"(b), "l"(c));
    return d;
}
__device__ __forceinline__ unsigned long long dup2(float v) {
    unsigned long long d;
    asm("mov.b64 %0, {%1, %1};" : "=l"(d) : "r"(__float_as_uint(v)));
    return d;
}
union P2 { unsigned long long u; float2 f; };
union W4 { float4 f4; unsigned long long u[2]; };
union H4 { uint4 u; __half2 h[4]; };

// ============ combined GEMM: blocks [0,nGg) do g-branch, rest do s-branch ============
__global__ __launch_bounds__(256) void gemm_both_kernel(
    const float* __restrict__ g, const float* __restrict__ x,
    const int* __restrict__ down_idx,
    const float* __restrict__ Wg, const float* __restrict__ Ws,
    int Ng, int nGg) {
    __shared__ float Wsm[CG * CN];   // 32 KB; s-branch: Ws in [0,4096), red in [4096,8192)
    __shared__ int ds[128];
    const int t = threadIdx.x;
    const int tr = t >> 3;
    const int c0 = (t & 7) * 8;
    const float4 zero4 = make_float4(0.f, 0.f, 0.f, 0.f);
    const int col = t & 63, seg = t >> 6;

    if (blockIdx.x < nGg) {
        // ---------------- g branch: fg = g @ Wg ----------------
        for (int i = t; i < CG * CN; i += 256) Wsm[i] = Wg[i];
        __syncthreads();
        const int r0 = blockIdx.x * 128 + tr * 4;

        unsigned long long acc[4][4];
#pragma unroll
        for (int j = 0; j < 4; j++)
#pragma unroll
            for (int i = 0; i < 4; i++) acc[j][i] = 0ull;

        bool v[4];
        const float4* gp[4];
#pragma unroll
        for (int j = 0; j < 4; j++) {
            v[j] = (r0 + j) < Ng;
            gp[j] = (const float4*)(g + (size_t)(r0 + j) * CG);
        }
#pragma unroll 2
        for (int k4 = 0; k4 < CG / 4; k4++) {
            float4 a[4];
#pragma unroll
            for (int j = 0; j < 4; j++) a[j] = v[j] ? __ldcs(&gp[j][k4]) : zero4;
#pragma unroll
            for (int kk = 0; kk < 4; kk++) {
                int k = k4 * 4 + kk;
                W4 w0, w1;
                w0.f4 = *(const float4*)&Wsm[k * CN + c0];
                w1.f4 = *(const float4*)&Wsm[k * CN + c0 + 4];
#pragma unroll
                for (int j = 0; j < 4; j++) {
                    unsigned long long av = dup2((&a[j].x)[kk]);
                    acc[j][0] = fma2(av, w0.u[0], acc[j][0]);
                    acc[j][1] = fma2(av, w0.u[1], acc[j][1]);
                    acc[j][2] = fma2(av, w1.u[0], acc[j][2]);
                    acc[j][3] = fma2(av, w1.u[1], acc[j][3]);
                }
            }
        }

        float csum[8], csq[8];
#pragma unroll
        for (int i = 0; i < 8; i++) { csum[i] = 0.f; csq[i] = 0.f; }
#pragma unroll
        for (int j = 0; j < 4; j++) {
            float av[8];
#pragma unroll
            for (int i = 0; i < 4; i++) {
                P2 p; p.u = acc[j][i];
                av[2 * i] = p.f.x; av[2 * i + 1] = p.f.y;
            }
            if (r0 + j < Ng) {
                H4 st;
#pragma unroll
                for (int i = 0; i < 4; i++)
                    st.h[i] = __floats2half2_rn(av[2 * i], av[2 * i + 1]);
                *(uint4*)&d_fg[(size_t)(r0 + j) * CN + c0] = st.u;
            }
#pragma unroll
            for (int i = 0; i < 8; i++) { csum[i] += av[i]; csq[i] += av[i] * av[i]; }
        }

        __syncthreads();
        float* s_sum = Wsm;
        float* s_sq  = Wsm + 2048;
#pragma unroll
        for (int i = 0; i < 8; i++) {
            s_sum[tr * 64 + c0 + i] = csum[i];
            s_sq[tr * 64 + c0 + i]  = csq[i];
        }
        __syncthreads();
        float v1 = 0.f, v2 = 0.f;
#pragma unroll
        for (int r = 0; r < 8; r++) {
            v1 += s_sum[(seg * 8 + r) * 64 + col];
            v2 += s_sq[(seg * 8 + r) * 64 + col];
        }
        __syncthreads();
        s_sum[seg * 64 + col] = v1;
        s_sq[seg * 64 + col]  = v2;
        __syncthreads();
        if (t < 64) {
            float a = s_sum[t] + s_sum[64 + t] + s_sum[128 + t] + s_sum[192 + t];
            float b = s_sq[t]  + s_sq[64 + t]  + s_sq[128 + t]  + s_sq[192 + t];
            atomicAdd(&d_colstats[t], a);
            atomicAdd(&d_colstats[64 + t], b);
        }
    } else {
        // ---------------- s branch: fs = x[down_idx] @ Ws ----------------
        for (int i = t; i < CS * CN; i += 256) Wsm[i] = Ws[i];
        const int rbase = (blockIdx.x - nGg) * 128;
        if (t < 128) ds[t] = (rbase + t < Ng) ? down_idx[rbase + t] : 0;
        __syncthreads();
        const int r0 = rbase + tr * 4;

        unsigned long long acc[4][4];
#pragma unroll
        for (int j = 0; j < 4; j++)
#pragma unroll
            for (int i = 0; i < 4; i++) acc[j][i] = 0ull;

        bool v[4];
        const float4* xp[4];
#pragma unroll
        for (int j = 0; j < 4; j++) {
            v[j] = (r0 + j) < Ng;
            xp[j] = (const float4*)(x + (size_t)ds[tr * 4 + j] * CS);
        }
#pragma unroll 2
        for (int k4 = 0; k4 < CS / 4; k4++) {
            float4 a[4];
#pragma unroll
            for (int j = 0; j < 4; j++) a[j] = v[j] ? __ldg(&xp[j][k4]) : zero4;
#pragma unroll
            for (int kk = 0; kk < 4; kk++) {
                int k = k4 * 4 + kk;
                W4 w0, w1;
                w0.f4 = *(const float4*)&Wsm[k * CN + c0];
                w1.f4 = *(const float4*)&Wsm[k * CN + c0 + 4];
#pragma unroll
                for (int j = 0; j < 4; j++) {
                    unsigned long long av = dup2((&a[j].x)[kk]);
                    acc[j][0] = fma2(av, w0.u[0], acc[j][0]);
                    acc[j][1] = fma2(av, w0.u[1], acc[j][1]);
                    acc[j][2] = fma2(av, w1.u[0], acc[j][2]);
                    acc[j][3] = fma2(av, w1.u[1], acc[j][3]);
                }
            }
        }

        float csum[8], csq[8];
#pragma unroll
        for (int i = 0; i < 8; i++) { csum[i] = 0.f; csq[i] = 0.f; }
#pragma unroll
        for (int j = 0; j < 4; j++) {
            float av[8];
#pragma unroll
            for (int i = 0; i < 4; i++) {
                P2 p; p.u = acc[j][i];
                av[2 * i] = p.f.x; av[2 * i + 1] = p.f.y;
            }
            if (r0 + j < Ng) {
                H4 st;
#pragma unroll
                for (int i = 0; i < 4; i++)
                    st.h[i] = __floats2half2_rn(av[2 * i], av[2 * i + 1]);
                *(uint4*)&d_fs[(size_t)(r0 + j) * CN + c0] = st.u;
            }
#pragma unroll
            for (int i = 0; i < 8; i++) { csum[i] += av[i]; csq[i] += av[i] * av[i]; }
        }

        // stats reduction in upper half of Wsm (not used by s-branch weights)
        float* s_sum = Wsm + 4096;
        float* s_sq  = Wsm + 6144;
#pragma unroll
        for (int i = 0; i < 8; i++) s_sum[tr * 64 + c0 + i] = csum[i];
        __syncthreads();
        float v1 = 0.f;
#pragma unroll
        for (int r = 0; r < 8; r++) v1 += s_sum[(seg * 8 + r) * 64 + col];
        __syncthreads();
        s_sum[seg * 64 + col] = v1;
        __syncthreads();
        if (t < 64) {
            float a = s_sum[t] + s_sum[64 + t] + s_sum[128 + t] + s_sum[192 + t];
            atomicAdd(&d_colstats[128 + t], a);
        }
        __syncthreads();
#pragma unroll
        for (int i = 0; i < 8; i++) s_sq[tr * 64 + c0 + i] = csq[i];
        __syncthreads();
        float v2 = 0.f;
#pragma unroll
        for (int r = 0; r < 8; r++) v2 += s_sq[(seg * 8 + r) * 64 + col];
        __syncthreads();
        s_sq[seg * 64 + col] = v2;
        __syncthreads();
        if (t < 64) {
            float b = s_sq[t] + s_sq[64 + t] + s_sq[128 + t] + s_sq[192 + t];
            atomicAdd(&d_colstats[192 + t], b);
        }
    }
}

// -------- fuse: z = (relu(bn_g(fg)) + relu(bn_s(fs))) . Wc; z-stats --------
__global__ __launch_bounds__(256) void fuse_kernel(
    const float* __restrict__ Wc,
    const float* __restrict__ gg, const float* __restrict__ bg,
    const float* __restrict__ gs, const float* __restrict__ bs, int Ng) {
    __shared__ float wc[CN], sgn[CN], bgn[CN], ssn[CN], bsn[CN];
    __shared__ float zs[8][2];
    int t = threadIdx.x;
    if (t < 128) {
        const int c = t & 63;
        const int br = t >> 6;
        float sum = d_colstats[br * 128 + c];
        float sq  = d_colstats[br * 128 + 64 + c];
        const float inv = 1.f / (float)Ng;
        float mu = sum * inv;
        float var = sq * inv - mu * mu;
        float gam = br ? __ldg(&gs[c]) : __ldg(&gg[c]);
        float bet = br ? __ldg(&bs[c]) : __ldg(&bg[c]);
        float sc = gam * rsqrtf(var + EPS);
        if (br == 0) { sgn[c] = sc; bgn[c] = bet - mu * sc; wc[c] = __ldg(&Wc[c]); }
        else         { ssn[c] = sc; bsn[c] = bet - mu * sc; }
    }
    __syncthreads();

    const int wid = t >> 5, lane = t & 31;
    const int rgrp = lane >> 3;
    const int cg = (lane & 7) * 8;
    float bsum = 0.f, bsq = 0.f;

    for (int rowb = (blockIdx.x * 8 + wid) * 8; rowb < Ng; rowb += gridDim.x * 64) {
        int row[2] = { rowb + rgrp, rowb + 4 + rgrp };
        H4 fgv[2], fsv[2];
#pragma unroll
        for (int q = 0; q < 2; q++) {
            if (row[q] < Ng) {
                fgv[q].u = __ldcs((const uint4*)&d_fg[(size_t)row[q] * CN + cg]);
                fsv[q].u = __ldcs((const uint4*)&d_fs[(size_t)row[q] * CN + cg]);
            }
        }
#pragma unroll
        for (int q = 0; q < 2; q++) {
            float part = 0.f;
            if (row[q] < Ng) {
#pragma unroll
                for (int i = 0; i < 4; i++) {
                    float2 f2 = __half22float2(fgv[q].h[i]);
                    float2 s2 = __half22float2(fsv[q].h[i]);
                    int c = cg + 2 * i;
                    float h0 = fmaxf(f2.x * sgn[c] + bgn[c], 0.f) + fmaxf(s2.x * ssn[c] + bsn[c], 0.f);
                    float h1 = fmaxf(f2.y * sgn[c + 1] + bgn[c + 1], 0.f) + fmaxf(s2.y * ssn[c + 1] + bsn[c + 1], 0.f);
                    part += h0 * wc[c] + h1 * wc[c + 1];
                }
            }
#pragma unroll
            for (int o = 4; o > 0; o >>= 1) part += __shfl_xor_sync(0xffffffffu, part, o);
            if ((lane & 7) == 0 && row[q] < Ng) {
                d_z[row[q]] = part;
                bsum += part;
                bsq += part * part;
            }
        }
    }
    bsum += __shfl_down_sync(0xffffffffu, bsum, 16);
    bsum += __shfl_down_sync(0xffffffffu, bsum, 8);
    bsq  += __shfl_down_sync(0xffffffffu, bsq, 16);
    bsq  += __shfl_down_sync(0xffffffffu, bsq, 8);
    if (lane == 0) { zs[wid][0] = bsum; zs[wid][1] = bsq; }
    __syncthreads();
    if (t == 0) {
        float a = 0.f, q = 0.f;
#pragma unroll
        for (int w = 0; w < 8; w++) { a += zs[w][0]; q += zs[w][1]; }
        atomicAdd(&d_zstats[0], a);
        atomicAdd(&d_zstats[1], q);
    }
}

// -------- scatter: gather z, inline BN+sigmoid, scatter into S --------
__global__ void scatter_kernel(const int* __restrict__ pin,
                               const int* __restrict__ pout,
                               const float* __restrict__ gamma_c,
                               const float* __restrict__ beta_c,
                               int P, float invNg) {
    float mu = d_zstats[0] * invNg;
    float var = d_zstats[1] * invNg - mu * mu;
    float rs = rsqrtf(var + EPS) * __ldg(&gamma_c[0]);
    float bc = __ldg(&beta_c[0]) - mu * rs;

    int i4 = (blockIdx.x * blockDim.x + threadIdx.x) * 4;
    int k = blockIdx.y;
    if (i4 + 3 < P) {
        uint4 pi = *(const uint4*)&pin[(size_t)k * P + i4];
        uint4 po = *(const uint4*)&pout[(size_t)k * P + i4];
        float z0 = __ldg(&d_z[pi.x]);
        float z1 = __ldg(&d_z[pi.y]);
        float z2 = __ldg(&d_z[pi.z]);
        float z3 = __ldg(&d_z[pi.w]);
        float a0 = 1.f / (1.f + __expf(-(z0 * rs + bc)));
        float a1 = 1.f / (1.f + __expf(-(z1 * rs + bc)));
        float a2 = 1.f / (1.f + __expf(-(z2 * rs + bc)));
        float a3 = 1.f / (1.f + __expf(-(z3 * rs + bc)));
        atomicAdd(&d_S[(size_t)po.x * KK + k], a0);
        atomicAdd(&d_S[(size_t)po.y * KK + k], a1);
        atomicAdd(&d_S[(size_t)po.z * KK + k], a2);
        atomicAdd(&d_S[(size_t)po.w * KK + k], a3);
    } else {
        for (int i = i4; i < P; i++) {
            float z = __ldg(&d_z[__ldg(&pin[(size_t)k * P + i])]);
            float a = 1.f / (1.f + __expf(-(z * rs + bc)));
            atomicAdd(&d_S[(size_t)__ldg(&pout[(size_t)k * P + i]) * KK + k], a);
        }
    }
}

// -------- out = x * (S @ W_inv + b_inv); warp = 8 rows/pass, MLP 16 --------
__global__ __launch_bounds__(256) void output_kernel(
    const float* __restrict__ x, const float* __restrict__ Winv,
    const float* __restrict__ binv, float* __restrict__ out, int Nx) {
    __shared__ float w[KK * CN];
    __shared__ float bb[CN];
    int t = threadIdx.x;
    for (int i = t; i < KK * CN; i += 256) w[i] = Winv[i];
    if (t < CN) bb[t] = binv[t];
    if (blockIdx.x == 0) {
        d_colstats[t] = 0.f;
        if (t < 2) d_zstats[t] = 0.f;
    }
    __syncthreads();
    const int wid = t >> 5, lane = t & 31;
    const int c = 2 * lane;
    const int r0 = (blockIdx.x * 8 + wid) * 8;
    if (r0 >= Nx) return;

    float sv[8];
    float2 xv[8];
#pragma unroll
    for (int j = 0; j < 8; j++)
        sv[j] = (lane < KK && r0 + j < Nx) ? __ldcs(&d_S[(size_t)(r0 + j) * KK + lane]) : 0.f;
#pragma unroll
    for (int j = 0; j < 8; j++)
        xv[j] = (r0 + j < Nx) ? __ldcs((const float2*)&x[(size_t)(r0 + j) * CS + c])
                              : make_float2(0.f, 0.f);
    // reset S for next invocation (read-before-write in program order)
#pragma unroll
    for (int j = 0; j < 8; j++)
        if (lane < KK && r0 + j < Nx) d_S[(size_t)(r0 + j) * KK + lane] = 0.f;

    float2 acc[8];
    const float b0 = bb[c], b1 = bb[c + 1];
#pragma unroll
    for (int j = 0; j < 8; j++) { acc[j].x = b0; acc[j].y = b1; }

#pragma unroll
    for (int k = 0; k < KK; k++) {
        float2 wk = *(const float2*)&w[k * CN + c];
#pragma unroll
        for (int j = 0; j < 8; j++) {
            float sk = __shfl_sync(0xffffffffu, sv[j], k);
            acc[j].x = fmaf(sk, wk.x, acc[j].x);
            acc[j].y = fmaf(sk, wk.y, acc[j].y);
        }
    }
#pragma unroll
    for (int j = 0; j < 8; j++) {
        if (r0 + j < Nx) {
            float2 o;
            o.x = xv[j].x * acc[j].x;
            o.y = xv[j].y * acc[j].y;
            __stcs((float2*)&out[(size_t)(r0 + j) * CS + c], o);
        }
    }
}

extern "C" void kernel_launch(void* const* d_in, const int* in_sizes, int n_in,
                              void* d_out, int out_size) {
    const float* g        = (const float*)d_in[0];
    const float* x        = (const float*)d_in[1];
    const int*   down_idx = (const int*)d_in[2];
    const int*   pairs_in = (const int*)d_in[3];
    const int*   pairs_out= (const int*)d_in[4];
    const float* Wg       = (const float*)d_in[5];
    const float* Ws       = (const float*)d_in[6];
    const float* Wc       = (const float*)d_in[7];
    const float* W_inv    = (const float*)d_in[8];
    const float* b_inv    = (const float*)d_in[9];
    const float* gamma_g  = (const float*)d_in[10];
    const float* beta_g   = (const float*)d_in[11];
    const float* gamma_s  = (const float*)d_in[12];
    const float* beta_s   = (const float*)d_in[13];
    const float* gamma_c  = (const float*)d_in[14];
    const float* beta_c   = (const float*)d_in[15];

    int Ng = in_sizes[0] / CG;
    int Nx = in_sizes[1] / CS;
    int KP = in_sizes[3];
    int P  = KP / KK;

    int nGg = (Ng + 127) / 128;
    gemm_both_kernel<<<2 * nGg, 256>>>(g, x, down_idx, Wg, Ws, Ng, nGg);
    fuse_kernel<<<(Ng + 63) / 64, 256>>>(Wc, gamma_g, beta_g, gamma_s, beta_s, Ng);
    dim3 sgrid(((P + 3) / 4 + 255) / 256, KK);
    scatter_kernel<<<sgrid, 256>>>(pairs_in, pairs_out, gamma_c, beta_c, P, 1.f / (float)Ng);
    output_kernel<<<(Nx + 63) / 64, 256>>>(x, W_inv, b_inv, (float*)d_out, Nx);
}

// round 14
// speedup vs baseline: 1.1793x; 1.0170x over previous
#include <cuda_runtime.h>
#include <cuda_fp16.h>
#include <math.h>

#define CG 128
#define CN 64
#define CS 64
#define KK 27
#define EPS 1e-5f

#define MAX_NG 60000
#define MAX_NX 200000

// -------- scratch (device globals, zero-initialized at module load) --------
// Invariant: every kernel_launch invocation leaves d_S, d_colstats, d_zstats
// zeroed for the next invocation (output_kernel resets during S read).
__device__ __half d_fg[MAX_NG * CN];
__device__ __half d_fs[MAX_NG * CN];
__device__ float d_z[MAX_NG];
__device__ float d_S[MAX_NX * KK];
__device__ float d_colstats[4 * CN];
__device__ float d_zstats[2];

// ---- packed f32x2 helpers (sm_103a FFMA2 via PTX) ----
__device__ __forceinline__ unsigned long long fma2(
    unsigned long long a, unsigned long long b, unsigned long long c) {
    unsigned long long d;
    asm("fma.rn.f32x2 %0, %1, %2, %3;" : "=l"(d) : "l"(a), "l"(b), "l"(c));
    return d;
}
__device__ __forceinline__ unsigned long long dup2(float v) {
    unsigned long long d;
    asm("mov.b64 %0, {%1, %1};" : "=l"(d) : "r"(__float_as_uint(v)));
    return d;
}
union P2 { unsigned long long u; float2 f; };
union W4 { float4 f4; unsigned long long u[2]; };
union H4 { uint4 u; __half2 h[4]; };

// ============ combined GEMM: blocks [0,nGg) do g-branch, rest do s-branch ============
__global__ __launch_bounds__(256) void gemm_both_kernel(
    const float* __restrict__ g, const float* __restrict__ x,
    const int* __restrict__ down_idx,
    const float* __restrict__ Wg, const float* __restrict__ Ws,
    int Ng, int nGg) {
    __shared__ float Wsm[CG * CN];   // 32 KB; s-branch: Ws in [0,4096), red in [4096,8192)
    __shared__ int ds[128];
    const int t = threadIdx.x;
    const int tr = t >> 3;
    const int c0 = (t & 7) * 8;
    const float4 zero4 = make_float4(0.f, 0.f, 0.f, 0.f);
    const int col = t & 63, seg = t >> 6;

    if (blockIdx.x < nGg) {
        // ---------------- g branch: fg = g @ Wg ----------------
        for (int i = t; i < CG * CN; i += 256) Wsm[i] = Wg[i];
        __syncthreads();
        const int r0 = blockIdx.x * 128 + tr * 4;

        unsigned long long acc[4][4];
#pragma unroll
        for (int j = 0; j < 4; j++)
#pragma unroll
            for (int i = 0; i < 4; i++) acc[j][i] = 0ull;

        bool v[4];
        const float4* gp[4];
#pragma unroll
        for (int j = 0; j < 4; j++) {
            v[j] = (r0 + j) < Ng;
            gp[j] = (const float4*)(g + (size_t)(r0 + j) * CG);
        }
#pragma unroll 2
        for (int k4 = 0; k4 < CG / 4; k4++) {
            float4 a[4];
#pragma unroll
            for (int j = 0; j < 4; j++) a[j] = v[j] ? __ldcs(&gp[j][k4]) : zero4;
#pragma unroll
            for (int kk = 0; kk < 4; kk++) {
                int k = k4 * 4 + kk;
                W4 w0, w1;
                w0.f4 = *(const float4*)&Wsm[k * CN + c0];
                w1.f4 = *(const float4*)&Wsm[k * CN + c0 + 4];
#pragma unroll
                for (int j = 0; j < 4; j++) {
                    unsigned long long av = dup2((&a[j].x)[kk]);
                    acc[j][0] = fma2(av, w0.u[0], acc[j][0]);
                    acc[j][1] = fma2(av, w0.u[1], acc[j][1]);
                    acc[j][2] = fma2(av, w1.u[0], acc[j][2]);
                    acc[j][3] = fma2(av, w1.u[1], acc[j][3]);
                }
            }
        }

        float csum[8], csq[8];
#pragma unroll
        for (int i = 0; i < 8; i++) { csum[i] = 0.f; csq[i] = 0.f; }
#pragma unroll
        for (int j = 0; j < 4; j++) {
            float av[8];
#pragma unroll
            for (int i = 0; i < 4; i++) {
                P2 p; p.u = acc[j][i];
                av[2 * i] = p.f.x; av[2 * i + 1] = p.f.y;
            }
            if (r0 + j < Ng) {
                H4 st;
#pragma unroll
                for (int i = 0; i < 4; i++)
                    st.h[i] = __floats2half2_rn(av[2 * i], av[2 * i + 1]);
                *(uint4*)&d_fg[(size_t)(r0 + j) * CN + c0] = st.u;
            }
#pragma unroll
            for (int i = 0; i < 8; i++) { csum[i] += av[i]; csq[i] += av[i] * av[i]; }
        }

        __syncthreads();
        float* s_sum = Wsm;
        float* s_sq  = Wsm + 2048;
#pragma unroll
        for (int i = 0; i < 8; i++) {
            s_sum[tr * 64 + c0 + i] = csum[i];
            s_sq[tr * 64 + c0 + i]  = csq[i];
        }
        __syncthreads();
        float v1 = 0.f, v2 = 0.f;
#pragma unroll
        for (int r = 0; r < 8; r++) {
            v1 += s_sum[(seg * 8 + r) * 64 + col];
            v2 += s_sq[(seg * 8 + r) * 64 + col];
        }
        __syncthreads();
        s_sum[seg * 64 + col] = v1;
        s_sq[seg * 64 + col]  = v2;
        __syncthreads();
        if (t < 64) {
            float a = s_sum[t] + s_sum[64 + t] + s_sum[128 + t] + s_sum[192 + t];
            float b = s_sq[t]  + s_sq[64 + t]  + s_sq[128 + t]  + s_sq[192 + t];
            atomicAdd(&d_colstats[t], a);
            atomicAdd(&d_colstats[64 + t], b);
        }
    } else {
        // ---------------- s branch: fs = x[down_idx] @ Ws ----------------
        for (int i = t; i < CS * CN; i += 256) Wsm[i] = Ws[i];
        const int rbase = (blockIdx.x - nGg) * 128;
        if (t < 128) ds[t] = (rbase + t < Ng) ? down_idx[rbase + t] : 0;
        __syncthreads();
        const int r0 = rbase + tr * 4;

        unsigned long long acc[4][4];
#pragma unroll
        for (int j = 0; j < 4; j++)
#pragma unroll
            for (int i = 0; i < 4; i++) acc[j][i] = 0ull;

        bool v[4];
        const float4* xp[4];
#pragma unroll
        for (int j = 0; j < 4; j++) {
            v[j] = (r0 + j) < Ng;
            xp[j] = (const float4*)(x + (size_t)ds[tr * 4 + j] * CS);
        }
#pragma unroll 2
        for (int k4 = 0; k4 < CS / 4; k4++) {
            float4 a[4];
#pragma unroll
            for (int j = 0; j < 4; j++) a[j] = v[j] ? __ldg(&xp[j][k4]) : zero4;
#pragma unroll
            for (int kk = 0; kk < 4; kk++) {
                int k = k4 * 4 + kk;
                W4 w0, w1;
                w0.f4 = *(const float4*)&Wsm[k * CN + c0];
                w1.f4 = *(const float4*)&Wsm[k * CN + c0 + 4];
#pragma unroll
                for (int j = 0; j < 4; j++) {
                    unsigned long long av = dup2((&a[j].x)[kk]);
                    acc[j][0] = fma2(av, w0.u[0], acc[j][0]);
                    acc[j][1] = fma2(av, w0.u[1], acc[j][1]);
                    acc[j][2] = fma2(av, w1.u[0], acc[j][2]);
                    acc[j][3] = fma2(av, w1.u[1], acc[j][3]);
                }
            }
        }

        float csum[8], csq[8];
#pragma unroll
        for (int i = 0; i < 8; i++) { csum[i] = 0.f; csq[i] = 0.f; }
#pragma unroll
        for (int j = 0; j < 4; j++) {
            float av[8];
#pragma unroll
            for (int i = 0; i < 4; i++) {
                P2 p; p.u = acc[j][i];
                av[2 * i] = p.f.x; av[2 * i + 1] = p.f.y;
            }
            if (r0 + j < Ng) {
                H4 st;
#pragma unroll
                for (int i = 0; i < 4; i++)
                    st.h[i] = __floats2half2_rn(av[2 * i], av[2 * i + 1]);
                *(uint4*)&d_fs[(size_t)(r0 + j) * CN + c0] = st.u;
            }
#pragma unroll
            for (int i = 0; i < 8; i++) { csum[i] += av[i]; csq[i] += av[i] * av[i]; }
        }

        // stats reduction in upper half of Wsm (not used by s-branch weights)
        float* s_sum = Wsm + 4096;
        float* s_sq  = Wsm + 6144;
#pragma unroll
        for (int i = 0; i < 8; i++) s_sum[tr * 64 + c0 + i] = csum[i];
        __syncthreads();
        float v1 = 0.f;
#pragma unroll
        for (int r = 0; r < 8; r++) v1 += s_sum[(seg * 8 + r) * 64 + col];
        __syncthreads();
        s_sum[seg * 64 + col] = v1;
        __syncthreads();
        if (t < 64) {
            float a = s_sum[t] + s_sum[64 + t] + s_sum[128 + t] + s_sum[192 + t];
            atomicAdd(&d_colstats[128 + t], a);
        }
        __syncthreads();
#pragma unroll
        for (int i = 0; i < 8; i++) s_sq[tr * 64 + c0 + i] = csq[i];
        __syncthreads();
        float v2 = 0.f;
#pragma unroll
        for (int r = 0; r < 8; r++) v2 += s_sq[(seg * 8 + r) * 64 + col];
        __syncthreads();
        s_sq[seg * 64 + col] = v2;
        __syncthreads();
        if (t < 64) {
            float b = s_sq[t] + s_sq[64 + t] + s_sq[128 + t] + s_sq[192 + t];
            atomicAdd(&d_colstats[192 + t], b);
        }
    }
}

// -------- fuse: z = (relu(bn_g(fg)) + relu(bn_s(fs))) . Wc; z-stats --------
__global__ __launch_bounds__(256) void fuse_kernel(
    const float* __restrict__ Wc,
    const float* __restrict__ gg, const float* __restrict__ bg,
    const float* __restrict__ gs, const float* __restrict__ bs, int Ng) {
    __shared__ float wc[CN], sgn[CN], bgn[CN], ssn[CN], bsn[CN];
    __shared__ float zs[8][2];
    int t = threadIdx.x;
    if (t < 128) {
        const int c = t & 63;
        const int br = t >> 6;
        float sum = d_colstats[br * 128 + c];
        float sq  = d_colstats[br * 128 + 64 + c];
        const float inv = 1.f / (float)Ng;
        float mu = sum * inv;
        float var = sq * inv - mu * mu;
        float gam = br ? __ldg(&gs[c]) : __ldg(&gg[c]);
        float bet = br ? __ldg(&bs[c]) : __ldg(&bg[c]);
        float sc = gam * rsqrtf(var + EPS);
        if (br == 0) { sgn[c] = sc; bgn[c] = bet - mu * sc; wc[c] = __ldg(&Wc[c]); }
        else         { ssn[c] = sc; bsn[c] = bet - mu * sc; }
    }
    __syncthreads();

    const int wid = t >> 5, lane = t & 31;
    const int rgrp = lane >> 3;
    const int cg = (lane & 7) * 8;
    float bsum = 0.f, bsq = 0.f;

    for (int rowb = (blockIdx.x * 8 + wid) * 8; rowb < Ng; rowb += gridDim.x * 64) {
        int row[2] = { rowb + rgrp, rowb + 4 + rgrp };
        H4 fgv[2], fsv[2];
#pragma unroll
        for (int q = 0; q < 2; q++) {
            if (row[q] < Ng) {
                fgv[q].u = __ldcs((const uint4*)&d_fg[(size_t)row[q] * CN + cg]);
                fsv[q].u = __ldcs((const uint4*)&d_fs[(size_t)row[q] * CN + cg]);
            }
        }
#pragma unroll
        for (int q = 0; q < 2; q++) {
            float part = 0.f;
            if (row[q] < Ng) {
#pragma unroll
                for (int i = 0; i < 4; i++) {
                    float2 f2 = __half22float2(fgv[q].h[i]);
                    float2 s2 = __half22float2(fsv[q].h[i]);
                    int c = cg + 2 * i;
                    float h0 = fmaxf(f2.x * sgn[c] + bgn[c], 0.f) + fmaxf(s2.x * ssn[c] + bsn[c], 0.f);
                    float h1 = fmaxf(f2.y * sgn[c + 1] + bgn[c + 1], 0.f) + fmaxf(s2.y * ssn[c + 1] + bsn[c + 1], 0.f);
                    part += h0 * wc[c] + h1 * wc[c + 1];
                }
            }
#pragma unroll
            for (int o = 4; o > 0; o >>= 1) part += __shfl_xor_sync(0xffffffffu, part, o);
            if ((lane & 7) == 0 && row[q] < Ng) {
                d_z[row[q]] = part;
                bsum += part;
                bsq += part * part;
            }
        }
    }
    bsum += __shfl_down_sync(0xffffffffu, bsum, 16);
    bsum += __shfl_down_sync(0xffffffffu, bsum, 8);
    bsq  += __shfl_down_sync(0xffffffffu, bsq, 16);
    bsq  += __shfl_down_sync(0xffffffffu, bsq, 8);
    if (lane == 0) { zs[wid][0] = bsum; zs[wid][1] = bsq; }
    __syncthreads();
    if (t == 0) {
        float a = 0.f, q = 0.f;
#pragma unroll
        for (int w = 0; w < 8; w++) { a += zs[w][0]; q += zs[w][1]; }
        atomicAdd(&d_zstats[0], a);
        atomicAdd(&d_zstats[1], q);
    }
}

// -------- scatter: gather z, inline BN+sigmoid, scatter into S --------
__global__ void scatter_kernel(const int* __restrict__ pin,
                               const int* __restrict__ pout,
                               const float* __restrict__ gamma_c,
                               const float* __restrict__ beta_c,
                               int P, float invNg) {
    float mu = d_zstats[0] * invNg;
    float var = d_zstats[1] * invNg - mu * mu;
    float rs = rsqrtf(var + EPS) * __ldg(&gamma_c[0]);
    float bc = __ldg(&beta_c[0]) - mu * rs;

    int i4 = (blockIdx.x * blockDim.x + threadIdx.x) * 4;
    int k = blockIdx.y;
    if (i4 + 3 < P) {
        uint4 pi = *(const uint4*)&pin[(size_t)k * P + i4];
        uint4 po = *(const uint4*)&pout[(size_t)k * P + i4];
        float z0 = __ldg(&d_z[pi.x]);
        float z1 = __ldg(&d_z[pi.y]);
        float z2 = __ldg(&d_z[pi.z]);
        float z3 = __ldg(&d_z[pi.w]);
        float a0 = 1.f / (1.f + __expf(-(z0 * rs + bc)));
        float a1 = 1.f / (1.f + __expf(-(z1 * rs + bc)));
        float a2 = 1.f / (1.f + __expf(-(z2 * rs + bc)));
        float a3 = 1.f / (1.f + __expf(-(z3 * rs + bc)));
        atomicAdd(&d_S[(size_t)po.x * KK + k], a0);
        atomicAdd(&d_S[(size_t)po.y * KK + k], a1);
        atomicAdd(&d_S[(size_t)po.z * KK + k], a2);
        atomicAdd(&d_S[(size_t)po.w * KK + k], a3);
    } else {
        for (int i = i4; i < P; i++) {
            float z = __ldg(&d_z[__ldg(&pin[(size_t)k * P + i])]);
            float a = 1.f / (1.f + __expf(-(z * rs + bc)));
            atomicAdd(&d_S[(size_t)__ldg(&pout[(size_t)k * P + i]) * KK + k], a);
        }
    }
}

// -------- out = x * (S @ W_inv + b_inv); warp = 8 rows/pass --------
// v5 (minimal): x loads moved AFTER the k-loop to shrink live-register span;
// __launch_bounds__(256,5) pins 5 blocks/SM for more latency-hiding warps.
__global__ __launch_bounds__(256, 5) void output_kernel(
    const float* __restrict__ x, const float* __restrict__ Winv,
    const float* __restrict__ binv, float* __restrict__ out, int Nx) {
    __shared__ float w[KK * CN];
    __shared__ float bb[CN];
    int t = threadIdx.x;
    for (int i = t; i < KK * CN; i += 256) w[i] = Winv[i];
    if (t < CN) bb[t] = binv[t];
    if (blockIdx.x == 0) {
        d_colstats[t] = 0.f;
        if (t < 2) d_zstats[t] = 0.f;
    }
    __syncthreads();
    const int wid = t >> 5, lane = t & 31;
    const int c = 2 * lane;
    const int r0 = (blockIdx.x * 8 + wid) * 8;
    if (r0 >= Nx) return;

    float sv[8];
#pragma unroll
    for (int j = 0; j < 8; j++)
        sv[j] = (lane < KK && r0 + j < Nx) ? __ldcs(&d_S[(size_t)(r0 + j) * KK + lane]) : 0.f;
    // reset S for next invocation (read-before-write in program order)
#pragma unroll
    for (int j = 0; j < 8; j++)
        if (lane < KK && r0 + j < Nx) d_S[(size_t)(r0 + j) * KK + lane] = 0.f;

    float2 acc[8];
    const float b0 = bb[c], b1 = bb[c + 1];
#pragma unroll
    for (int j = 0; j < 8; j++) { acc[j].x = b0; acc[j].y = b1; }

#pragma unroll
    for (int k = 0; k < KK; k++) {
        float2 wk = *(const float2*)&w[k * CN + c];
#pragma unroll
        for (int j = 0; j < 8; j++) {
            float sk = __shfl_sync(0xffffffffu, sv[j], k);
            acc[j].x = fmaf(sk, wk.x, acc[j].x);
            acc[j].y = fmaf(sk, wk.y, acc[j].y);
        }
    }

    // x loads AFTER the k-loop: not live across it -> lower register pressure
    float2 xv[8];
#pragma unroll
    for (int j = 0; j < 8; j++)
        xv[j] = (r0 + j < Nx) ? __ldcs((const float2*)&x[(size_t)(r0 + j) * CS + c])
                              : make_float2(0.f, 0.f);
#pragma unroll
    for (int j = 0; j < 8; j++) {
        if (r0 + j < Nx) {
            float2 o;
            o.x = xv[j].x * acc[j].x;
            o.y = xv[j].y * acc[j].y;
            __stcs((float2*)&out[(size_t)(r0 + j) * CS + c], o);
        }
    }
}

extern "C" void kernel_launch(void* const* d_in, const int* in_sizes, int n_in,
                              void* d_out, int out_size) {
    const float* g        = (const float*)d_in[0];
    const float* x        = (const float*)d_in[1];
    const int*   down_idx = (const int*)d_in[2];
    const int*   pairs_in = (const int*)d_in[3];
    const int*   pairs_out= (const int*)d_in[4];
    const float* Wg       = (const float*)d_in[5];
    const float* Ws       = (const float*)d_in[6];
    const float* Wc       = (const float*)d_in[7];
    const float* W_inv    = (const float*)d_in[8];
    const float* b_inv    = (const float*)d_in[9];
    const float* gamma_g  = (const float*)d_in[10];
    const float* beta_g   = (const float*)d_in[11];
    const float* gamma_s  = (const float*)d_in[12];
    const float* beta_s   = (const float*)d_in[13];
    const float* gamma_c  = (const float*)d_in[14];
    const float* beta_c   = (const float*)d_in[15];

    int Ng = in_sizes[0] / CG;
    int Nx = in_sizes[1] / CS;
    int KP = in_sizes[3];
    int P  = KP / KK;

    int nGg = (Ng + 127) / 128;
    gemm_both_kernel<<<2 * nGg, 256>>>(g, x, down_idx, Wg, Ws, Ng, nGg);
    fuse_kernel<<<(Ng + 63) / 64, 256>>>(Wc, gamma_g, beta_g, gamma_s, beta_s, Ng);
    dim3 sgrid(((P + 3) / 4 + 255) / 256, KK);
    scatter_kernel<<<sgrid, 256>>>(pairs_in, pairs_out, gamma_c, beta_c, P, 1.f / (float)Ng);
    output_kernel<<<(Nx + 63) / 64, 256>>>(x, W_inv, b_inv, (float*)d_out, Nx);
}